// round 15
// baseline (speedup 1.0000x reference)
#include <cuda_runtime.h>
#include <cuda_bf16.h>
#include <cstdint>
#include <math.h>

#define D_MODEL 1024
#define NUM_HEADS 16
#define D_K 64
#define D_FF 4096
#define BATCH 2
#define SEQ 2048
#define TOK (BATCH*SEQ)
#define BH (BATCH*NUM_HEADS)
typedef __nv_bfloat16 bf16;

// ---- scratch ----
__device__ bf16 g_xh[(size_t)TOK*D_MODEL], g_xl[(size_t)TOK*D_MODEL];
__device__ bf16 g_wqkvh[(size_t)3072*D_MODEL], g_wqkvl[(size_t)3072*D_MODEL];
__device__ bf16 g_woh[(size_t)D_MODEL*D_MODEL], g_wol[(size_t)D_MODEL*D_MODEL];
__device__ bf16 g_w1h[(size_t)D_FF*D_MODEL],  g_w1l[(size_t)D_FF*D_MODEL];
__device__ bf16 g_w2h[(size_t)D_MODEL*D_FF],  g_w2l[(size_t)D_MODEL*D_FF];
__device__ float g_bqkv[3072];
__device__ bf16 g_qkvh[(size_t)TOK*3072], g_qkvl[(size_t)TOK*3072];
__device__ bf16 g_vth[(size_t)BH*D_K*SEQ], g_vtl[(size_t)BH*D_K*SEQ];
__device__ float g_m[(size_t)BH*SEQ], g_l[(size_t)BH*SEQ];
__device__ bf16 g_ch[(size_t)TOK*D_MODEL], g_cl[(size_t)TOK*D_MODEL];
__device__ bf16 g_hh[(size_t)TOK*D_MODEL], g_hl[(size_t)TOK*D_MODEL];
__device__ bf16 g_ffh[(size_t)TOK*D_FF],   g_ffl[(size_t)TOK*D_FF];
__device__ float g_y[(size_t)TOK*D_MODEL];
__device__ float g_h[(size_t)TOK*D_MODEL];

// ---- helpers ----
__device__ __forceinline__ uint32_t smem_u32(const void* p){
    uint32_t a;
    asm("{ .reg .u64 t; cvta.to.shared.u64 t, %1; cvt.u32.u64 %0, t; }" : "=r"(a) : "l"(p));
    return a;
}
__device__ __forceinline__ void f2pair(float f, bf16& h, bf16& l){
    h = __float2bfloat16(f);
    l = __float2bfloat16(f - __bfloat162float(h));
}
__device__ __forceinline__ void pack_hl(float a, float b, uint32_t& hi, uint32_t& lo){
    bf16 ah = __float2bfloat16(a), bh = __float2bfloat16(b);
    bf16 al = __float2bfloat16(a - __bfloat162float(ah));
    bf16 bl = __float2bfloat16(b - __bfloat162float(bh));
    __nv_bfloat162 h2(ah, bh), l2(al, bl);
    hi = *(uint32_t*)&h2; lo = *(uint32_t*)&l2;
}
#define CP16(d, s) asm volatile("cp.async.cg.shared.global [%0], [%1], 16;" :: "r"(d), "l"(s))
#define CP_COMMIT() asm volatile("cp.async.commit_group;" ::: "memory")
#define CP_WAIT(n) asm volatile("cp.async.wait_group %0;" :: "n"(n) : "memory")
#define MMA(c, a, b0, b1) \
    asm volatile("mma.sync.aligned.m16n8k16.row.col.f32.bf16.bf16.f32 " \
        "{%0,%1,%2,%3},{%4,%5,%6,%7},{%8,%9},{%0,%1,%2,%3};" \
        : "+f"((c)[0]),"+f"((c)[1]),"+f"((c)[2]),"+f"((c)[3]) \
        : "r"((a)[0]),"r"((a)[1]),"r"((a)[2]),"r"((a)[3]),"r"(b0),"r"(b1))
__device__ __forceinline__ void ldm4(uint32_t* r, uint32_t addr){
    asm volatile("ldmatrix.sync.aligned.m8n8.x4.shared.b16 {%0,%1,%2,%3}, [%4];"
        : "=r"(r[0]),"=r"(r[1]),"=r"(r[2]),"=r"(r[3]) : "r"(addr));
}
__device__ __forceinline__ void red_add(float* p, float v){
    asm volatile("red.global.add.f32 [%0], %1;" :: "l"(p), "f"(v) : "memory");
}

// ---- conversions ----
__global__ void conv_pair_k(const float* __restrict__ s, bf16* __restrict__ h, bf16* __restrict__ l, long n){
    long i = (long)blockIdx.x*blockDim.x + threadIdx.x;
    if(i < n){ bf16 a,b; f2pair(s[i],a,b); h[i]=a; l[i]=b; }
}
__global__ void concat_bias_k(const float* a, const float* b, const float* c, float* o){
    int i = blockIdx.x*256 + threadIdx.x;
    if(i < 3072) o[i] = (i < 1024) ? a[i] : (i < 2048) ? b[i-1024] : c[i-2048];
}
// y[r][c] = bias[c], vectorized
__global__ void binit_k(float* __restrict__ y, const float* __restrict__ bias){
    long i = ((long)blockIdx.x*256 + threadIdx.x)*4;
    int c = (int)(i & (D_MODEL-1));
    *(float4*)(y+i) = *(const float4*)(bias+c);
}
__global__ void wtrans_k(const float* __restrict__ W, bf16* __restrict__ th, bf16* __restrict__ tl, int K, int N){
    __shared__ float t[32][33];
    int n0 = blockIdx.x*32, k0 = blockIdx.y*32;
#pragma unroll
    for(int r=0;r<4;r++) t[threadIdx.y+r*8][threadIdx.x] = W[(long)(k0+threadIdx.y+r*8)*N + n0+threadIdx.x];
    __syncthreads();
#pragma unroll
    for(int r=0;r<4;r++){
        int n = n0+threadIdx.y+r*8;
        bf16 a,b; f2pair(t[threadIdx.x][threadIdx.y+r*8],a,b);
        th[(long)n*K + k0+threadIdx.x]=a; tl[(long)n*K + k0+threadIdx.x]=b;
    }
}
__global__ void vtrans_k(const bf16* __restrict__ vh, const bf16* __restrict__ vl, int lda,
                         bf16* __restrict__ oth, bf16* __restrict__ otl){
    __shared__ bf16 th_[32][33], tl_[32][33];
    int bz = blockIdx.z, bb = bz/NUM_HEADS, hh = bz%NUM_HEADS;
    int s0 = blockIdx.x*32, n0 = blockIdx.y*32;
#pragma unroll
    for(int r=0;r<4;r++){
        long src = (long)(bb*SEQ + s0+threadIdx.y+r*8)*lda + hh*D_K + n0+threadIdx.x;
        th_[threadIdx.y+r*8][threadIdx.x] = vh[src];
        tl_[threadIdx.y+r*8][threadIdx.x] = vl[src];
    }
    __syncthreads();
#pragma unroll
    for(int r=0;r<4;r++){
        long dst = ((long)bz*D_K + n0+threadIdx.y+r*8)*SEQ + s0+threadIdx.x;
        oth[dst] = th_[threadIdx.x][threadIdx.y+r*8];
        otl[dst] = tl_[threadIdx.x][threadIdx.y+r*8];
    }
}

// ---- dense split-bf16 GEMM, BK=64, 3-stage ring, optional atomic split-K ----
template<int TN, int OUT, bool RELU, int STAGES, int SPLITK>
__global__ void __launch_bounds__(256) gemm_mma(
    const bf16* __restrict__ Ah, const bf16* __restrict__ Al,
    const bf16* __restrict__ Bh, const bf16* __restrict__ Bl,
    const float* __restrict__ bias,
    float* __restrict__ Cf, bf16* __restrict__ Ch, bf16* __restrict__ Cl,
    int K, int lda, int ldb, int ldc, float alpha)
{
    constexpr int PADK = 72;
    constexpr int SA = 128*PADK;
    constexpr int SB = TN*PADK;
    constexpr int STG = 2*(SA+SB);
    constexpr int NTILES = TN/16;
    constexpr int NP = NTILES/2;
    constexpr int BCH = TN/32;

    extern __shared__ bf16 sm[];
    const int tid = threadIdx.x, wid = tid>>5, lane = tid&31;
    const int warp_m = wid & 3, warp_n = wid >> 2;
    const int g = lane>>2, t2 = (lane&3)*2;
    const int row0 = blockIdx.y*128, col0 = blockIdx.x*TN;

    const int Keff = K/SPLITK;
    const int kb0 = (SPLITK>1) ? blockIdx.z*Keff : 0;
    Ah += kb0; Al += kb0; Bh += kb0; Bl += kb0;

    int aoff[2];
#pragma unroll
    for(int mt=0; mt<2; mt++)
        aoff[mt] = (warp_m*32 + mt*16 + (lane&7) + ((lane>>3)&1)*8)*PADK + ((lane>>4)<<3);
    int boff[NP];
#pragma unroll
    for(int p=0; p<NP; p++)
        boff[p] = (warp_n*(TN/2) + p*16 + ((lane>>4)<<3) + (lane&7))*PADK + ((lane>>3)&1)*8;

    float acc[2][NTILES][4];
#pragma unroll
    for(int i=0;i<2;i++)
#pragma unroll
        for(int j=0;j<NTILES;j++)
#pragma unroll
            for(int e=0;e<4;e++) acc[i][j][e]=0.f;

    const int NT = Keff/64;

    auto issue = [&](int stage, int kb){
        bf16* st = sm + (stage % STAGES)*STG;
#pragma unroll
        for(int c=0;c<4;c++){
            int cid = tid + c*256, r = cid>>3, k8 = (cid&7)*8;
            CP16(smem_u32(st + r*PADK + k8),      Ah + (long)(row0+r)*lda + kb + k8);
            CP16(smem_u32(st + SA + r*PADK + k8), Al + (long)(row0+r)*lda + kb + k8);
        }
#pragma unroll
        for(int c=0;c<BCH;c++){
            int cid = tid + c*256, n = cid>>3, k8 = (cid&7)*8;
            CP16(smem_u32(st + 2*SA + n*PADK + k8),      Bh + (long)(col0+n)*ldb + kb + k8);
            CP16(smem_u32(st + 2*SA + SB + n*PADK + k8), Bl + (long)(col0+n)*ldb + kb + k8);
        }
        CP_COMMIT();
    };

    auto compute = [&](int stage){
        const uint32_t uAh = smem_u32(sm + (stage % STAGES)*STG);
        const uint32_t uAl = uAh + SA*2;
        const uint32_t uBh = uAh + 2*SA*2;
        const uint32_t uBl = uAh + (2*SA+SB)*2;
#pragma unroll
        for(int ks=0; ks<4; ks++){
            const int kc = ks*16;
            uint32_t fAh[2][4], fAl[2][4];
#pragma unroll
            for(int mt=0; mt<2; mt++){
                ldm4(fAh[mt], uAh + (aoff[mt]+kc)*2);
                ldm4(fAl[mt], uAl + (aoff[mt]+kc)*2);
            }
#pragma unroll
            for(int p=0; p<NP; p++){
                uint32_t bh[4], bl[4];
                ldm4(bh, uBh + (boff[p]+kc)*2);
                ldm4(bl, uBl + (boff[p]+kc)*2);
#pragma unroll
                for(int s=0; s<2; s++){
                    const int nt = p*2 + s;
#pragma unroll
                    for(int mt=0; mt<2; mt++){
                        MMA(acc[mt][nt], fAh[mt], bh[s*2], bh[s*2+1]);
                        MMA(acc[mt][nt], fAh[mt], bl[s*2], bl[s*2+1]);
                        MMA(acc[mt][nt], fAl[mt], bh[s*2], bh[s*2+1]);
                    }
                }
            }
        }
    };

#pragma unroll
    for(int s=0; s<STAGES-1; s++) if(s < NT) issue(s, s*64);
    for(int i=0; i<NT; i++){
        if(i+1 < NT) CP_WAIT(1); else CP_WAIT(0);
        __syncthreads();
        compute(i);
        if(i+STAGES-1 < NT) issue(i+STAGES-1, (i+STAGES-1)*64);
    }

#pragma unroll
    for(int mt=0; mt<2; mt++){
#pragma unroll
        for(int nt=0; nt<NTILES; nt++){
            int r = row0 + warp_m*32 + mt*16 + g;
            int c = col0 + warp_n*(TN/2) + nt*8 + t2;
            float b0 = (bias && SPLITK==1) ? bias[c]   : 0.f;
            float b1 = (bias && SPLITK==1) ? bias[c+1] : 0.f;
#pragma unroll
            for(int half=0; half<2; half++){
                int rr = r + half*8;
                float v0 = acc[mt][nt][half*2+0]*alpha + b0;
                float v1 = acc[mt][nt][half*2+1]*alpha + b1;
                if(RELU){ v0 = fmaxf(v0,0.f); v1 = fmaxf(v1,0.f); }
                long idx = (long)rr*ldc + c;
                if(OUT==0){
                    if(SPLITK>1){ red_add(Cf+idx, v0); red_add(Cf+idx+1, v1); }
                    else *(float2*)(Cf + idx) = make_float2(v0, v1);
                } else {
                    bf16 h0,l0,h1,l1; f2pair(v0,h0,l0); f2pair(v1,h1,l1);
                    *(__nv_bfloat162*)(Ch + idx) = __nv_bfloat162(h0, h1);
                    *(__nv_bfloat162*)(Cl + idx) = __nv_bfloat162(l0, l1);
                }
            }
        }
    }
}

// ==================== fused attention (R11 proven) ====================
#define FA_OFF_Q 0
#define FA_OFF_K 18432
#define FA_STG_K 18432
#define FA_OFF_MASK (FA_OFF_K + 2*FA_STG_K)
#define FA_OFF_RED  (FA_OFF_MASK + 1024)
#define FA_SMEM     (FA_OFF_RED + 2048)

__global__ void attn_ml_k(const bf16* __restrict__ qh, const int* __restrict__ mask,
                          float* __restrict__ gm, float* __restrict__ gl)
{
    extern __shared__ char smc[];
    const uint32_t sb = smem_u32(smc);
    const int tid=threadIdx.x, wid=tid>>5, lane=tid&31;
    const int warp_m=wid&3, warp_n=wid>>2, g=lane>>2, t2=(lane&3)*2;
    const int bz=blockIdx.z, bb=bz>>4, hh=bz&15;
    const int row0=blockIdx.x*128;
    int aoffQ[2];
#pragma unroll
    for(int mt=0;mt<2;mt++)
        aoffQ[mt] = (warp_m*32 + mt*16 + (lane&7) + ((lane>>3)&1)*8)*72 + ((lane>>4)<<3);
    int boffK[4];
#pragma unroll
    for(int p=0;p<4;p++)
        boffK[p] = (warp_n*64 + p*16 + ((lane>>4)<<3) + (lane&7))*72 + ((lane>>3)&1)*8;

    const bf16* Qh = qh + ((long)bb*SEQ+row0)*3072 + hh*64;
    const bf16* Kh = qh + 1024 + (long)bb*SEQ*3072 + hh*64;
    const int* mrow = mask + (long)bb*SEQ;

    auto issueK = [&](int j){
#pragma unroll
        for(int c=0;c<4;c++){ int cid=tid+c*256, r=cid>>3, ch=cid&7;
            CP16(sb + FA_OFF_K + (j&1)*FA_STG_K + (r*72+ch*8)*2, Kh + (long)(j*128+r)*3072 + ch*8);
        }
        if(tid < 32) CP16(sb + FA_OFF_MASK + (j&1)*512 + tid*16, mrow + j*128 + tid*4);
        CP_COMMIT();
    };

#pragma unroll
    for(int c=0;c<4;c++){ int cid=tid+c*256, r=cid>>3, ch=cid&7;
        CP16(sb + FA_OFF_Q + (r*72+ch*8)*2, Qh + (long)r*3072 + ch*8);
    }
    issueK(0);
    issueK(1);

    float m_[2][2], l_[2][2];
#pragma unroll
    for(int mt=0;mt<2;mt++){ m_[mt][0]=m_[mt][1]=-1e30f; l_[mt][0]=l_[mt][1]=0.f; }

    float sacc[2][8][4];
    for(int j=0;j<16;j++){
        if(j+1<16) CP_WAIT(1); else CP_WAIT(0);
        __syncthreads();
#pragma unroll
        for(int mt=0;mt<2;mt++)
#pragma unroll
            for(int nt=0;nt<8;nt++)
#pragma unroll
                for(int e=0;e<4;e++) sacc[mt][nt][e]=0.f;
        {
            uint32_t uQh = sb+FA_OFF_Q;
            uint32_t uKh = sb+FA_OFF_K+(j&1)*FA_STG_K;
#pragma unroll
            for(int ks=0;ks<4;ks++){
                const int kc = ks*16;
                uint32_t fQh[2][4];
#pragma unroll
                for(int mt=0;mt<2;mt++) ldm4(fQh[mt], uQh + (aoffQ[mt]+kc)*2);
#pragma unroll
                for(int p=0;p<4;p++){
                    uint32_t bh[4];
                    ldm4(bh, uKh + (boffK[p]+kc)*2);
#pragma unroll
                    for(int s2=0;s2<2;s2++){
                        const int nt = p*2+s2;
#pragma unroll
                        for(int mt=0;mt<2;mt++)
                            MMA(sacc[mt][nt], fQh[mt], bh[s2*2], bh[s2*2+1]);
                    }
                }
            }
        }
        const int* msk = (const int*)(smc + FA_OFF_MASK + (j&1)*512);
#pragma unroll
        for(int mt=0;mt<2;mt++)
#pragma unroll
            for(int nt=0;nt<8;nt++)
#pragma unroll
                for(int e=0;e<4;e++){
                    int col = warp_n*64 + nt*8 + t2 + (e&1);
                    sacc[mt][nt][e] = msk[col] ? sacc[mt][nt][e]*0.125f : -1e9f;
                }
#pragma unroll
        for(int mt=0;mt<2;mt++)
#pragma unroll
            for(int half=0; half<2; half++){
                float tmax = -1e30f;
#pragma unroll
                for(int nt=0;nt<8;nt++) tmax = fmaxf(tmax, fmaxf(sacc[mt][nt][half*2], sacc[mt][nt][half*2+1]));
                float mo = m_[mt][half];
                float mn = fmaxf(mo, tmax);
                float acc = l_[mt][half]*__expf(mo-mn);
#pragma unroll
                for(int nt=0;nt<8;nt++)
                    acc += __expf(sacc[mt][nt][half*2]-mn) + __expf(sacc[mt][nt][half*2+1]-mn);
                m_[mt][half]=mn; l_[mt][half]=acc;
            }
        __syncthreads();
        if(j+2<16) issueK(j+2);
    }
#pragma unroll
    for(int mt=0;mt<2;mt++)
#pragma unroll
        for(int half=0; half<2; half++){
            float m = m_[mt][half], l = l_[mt][half];
#pragma unroll
            for(int o=1;o<=2;o<<=1){
                float om = __shfl_xor_sync(0xffffffffu, m, o);
                float ol = __shfl_xor_sync(0xffffffffu, l, o);
                float mm = fmaxf(m, om);
                l = l*__expf(m-mm) + ol*__expf(om-mm);
                m = mm;
            }
            m_[mt][half]=m; l_[mt][half]=l;
        }
    float* rm = (float*)(smc + FA_OFF_RED);
    float* rl = rm + 256;
    if((lane&3)==0){
#pragma unroll
        for(int mt=0;mt<2;mt++)
#pragma unroll
            for(int half=0; half<2; half++){
                int row = warp_m*32 + mt*16 + half*8 + g;
                rm[warp_n*128+row] = m_[mt][half];
                rl[warp_n*128+row] = l_[mt][half];
            }
    }
    __syncthreads();
    if(tid < 128){
        float m0=rm[tid], m1=rm[128+tid], l0=rl[tid], l1=rl[128+tid];
        float mm = fmaxf(m0, m1);
        float ll = l0*__expf(m0-mm) + l1*__expf(m1-mm);
        gm[(long)bz*SEQ + row0 + tid] = mm;
        gl[(long)bz*SEQ + row0 + tid] = ll;
    }
}

#define PB_OFF_Q 0
#define PB_OFF_K 36864
#define PB_OFF_VT (PB_OFF_K + 36864)
#define PB_OFF_MASK (PB_OFF_VT + 34816)
#define PB_SMEM (PB_OFF_MASK + 512)

__global__ void __launch_bounds__(256,2) attn_pv_k(
    const bf16* __restrict__ qh, const bf16* __restrict__ ql,
    const bf16* __restrict__ vth, const bf16* __restrict__ vtl,
    const int* __restrict__ mask,
    const float* __restrict__ gm, const float* __restrict__ gl,
    float* __restrict__ attn, bf16* __restrict__ ch, bf16* __restrict__ cl)
{
    extern __shared__ char smc[];
    const uint32_t sb = smem_u32(smc);
    const int tid=threadIdx.x, wid=tid>>5, lane=tid&31;
    const int g=lane>>2, t2=(lane&3)*2;
    const int bz=blockIdx.z, bb=bz>>4, hh=bz&15;
    const int row0=blockIdx.x*128;

    const int aoffQ = (wid*16 + (lane&7) + ((lane>>3)&1)*8)*72 + ((lane>>4)<<3);
    int boffK[4];
#pragma unroll
    for(int p=0;p<4;p++)
        boffK[p] = (p*16 + ((lane>>4)<<3) + (lane&7))*72 + ((lane>>3)&1)*8;
    int boffV[4];
#pragma unroll
    for(int p=0;p<4;p++)
        boffV[p] = (p*16 + ((lane>>4)<<3) + (lane&7))*136 + ((lane>>3)&1)*8;

    const bf16* Qh = qh + ((long)bb*SEQ+row0)*3072 + hh*64;
    const bf16* Ql = ql + ((long)bb*SEQ+row0)*3072 + hh*64;
    const bf16* Kh = qh + 1024 + (long)bb*SEQ*3072 + hh*64;
    const bf16* Kl = ql + 1024 + (long)bb*SEQ*3072 + hh*64;
    const bf16* Vh = vth + (long)bz*D_K*SEQ;
    const bf16* Vl = vtl + (long)bz*D_K*SEQ;
    const int* mrow = mask + (long)bb*SEQ;

    float m_[2], il_[2];
#pragma unroll
    for(int half=0; half<2; half++){
        long row = (long)bz*SEQ + row0 + wid*16 + half*8 + g;
        m_[half] = gm[row];
        il_[half] = 1.f / gl[row];
    }

    float oacc[8][4];
#pragma unroll
    for(int nt=0;nt<8;nt++)
#pragma unroll
        for(int e=0;e<4;e++) oacc[nt][e]=0.f;

#pragma unroll
    for(int c=0;c<4;c++){ int cid=tid+c*256, r=cid>>3, ch8=cid&7;
        CP16(sb + PB_OFF_Q + (r*72+ch8*8)*2,         Qh + (long)r*3072 + ch8*8);
        CP16(sb + PB_OFF_Q + 18432 + (r*72+ch8*8)*2, Ql + (long)r*3072 + ch8*8);
    }

    for(int j=0;j<16;j++){
        if(j>0) __syncthreads();
#pragma unroll
        for(int c=0;c<4;c++){ int cid=tid+c*256, r=cid>>3, ch8=cid&7;
            CP16(sb + PB_OFF_K + (r*72+ch8*8)*2,         Kh + (long)(j*128+r)*3072 + ch8*8);
            CP16(sb + PB_OFF_K + 18432 + (r*72+ch8*8)*2, Kl + (long)(j*128+r)*3072 + ch8*8);
        }
#pragma unroll
        for(int c=0;c<4;c++){ int cid=tid+c*256, r=cid>>4, ch8=cid&15;
            CP16(sb + PB_OFF_VT + (r*136+ch8*8)*2,         Vh + (long)r*SEQ + j*128 + ch8*8);
            CP16(sb + PB_OFF_VT + 17408 + (r*136+ch8*8)*2, Vl + (long)r*SEQ + j*128 + ch8*8);
        }
        if(tid < 32) CP16(sb + PB_OFF_MASK + tid*16, mrow + j*128 + tid*4);
        CP_COMMIT();
        CP_WAIT(0);
        __syncthreads();

        const uint32_t uQh = sb+PB_OFF_Q, uQl = uQh+18432;
        const uint32_t uKh = sb+PB_OFF_K, uKl = uKh+18432;
        const uint32_t uVh = sb+PB_OFF_VT, uVl = uVh+17408;
        const int* msk = (const int*)(smc + PB_OFF_MASK);

#pragma unroll
        for(int khalf=0; khalf<2; khalf++){
            const int kb = khalf*64;
            float sacc[8][4];
#pragma unroll
            for(int nt=0;nt<8;nt++)
#pragma unroll
                for(int e=0;e<4;e++) sacc[nt][e]=0.f;
#pragma unroll
            for(int ks=0;ks<4;ks++){
                const int kc = ks*16;
                uint32_t fQh[4], fQl[4];
                ldm4(fQh, uQh + (aoffQ+kc)*2);
                ldm4(fQl, uQl + (aoffQ+kc)*2);
#pragma unroll
                for(int p=0;p<4;p++){
                    uint32_t bh[4], bl[4];
                    ldm4(bh, uKh + (boffK[p]+kb*72+kc)*2);
                    ldm4(bl, uKl + (boffK[p]+kb*72+kc)*2);
#pragma unroll
                    for(int s2=0;s2<2;s2++){
                        const int nt = p*2+s2;
                        MMA(sacc[nt], fQh, bh[s2*2], bh[s2*2+1]);
                        MMA(sacc[nt], fQh, bl[s2*2], bl[s2*2+1]);
                        MMA(sacc[nt], fQl, bh[s2*2], bh[s2*2+1]);
                    }
                }
            }
#pragma unroll
            for(int nt=0;nt<8;nt++)
#pragma unroll
                for(int e=0;e<4;e++){
                    int col = kb + nt*8 + t2 + (e&1);
                    float sv = msk[col] ? sacc[nt][e]*0.125f : -1e9f;
                    sacc[nt][e] = __expf(sv - m_[e>>1]) * il_[e>>1];
                }
#pragma unroll
            for(int nt=0;nt<8;nt++)
#pragma unroll
                for(int half=0; half<2; half++){
                    long r = row0 + wid*16 + half*8 + g;
                    *(float2*)(attn + (long)bz*SEQ*SEQ + r*SEQ + j*128 + kb + nt*8 + t2)
                        = make_float2(sacc[nt][half*2], sacc[nt][half*2+1]);
                }
#pragma unroll
            for(int s=0;s<4;s++){
                uint32_t phi[4], plo[4];
                pack_hl(sacc[2*s  ][0], sacc[2*s  ][1], phi[0], plo[0]);
                pack_hl(sacc[2*s  ][2], sacc[2*s  ][3], phi[1], plo[1]);
                pack_hl(sacc[2*s+1][0], sacc[2*s+1][1], phi[2], plo[2]);
                pack_hl(sacc[2*s+1][2], sacc[2*s+1][3], phi[3], plo[3]);
                const int koff = kb + s*16;
#pragma unroll
                for(int pd=0;pd<4;pd++){
                    uint32_t bh[4], bl[4];
                    ldm4(bh, uVh + (boffV[pd]+koff)*2);
                    ldm4(bl, uVl + (boffV[pd]+koff)*2);
#pragma unroll
                    for(int s2=0;s2<2;s2++){
                        const int ntd = pd*2+s2;
                        MMA(oacc[ntd], phi, bh[s2*2], bh[s2*2+1]);
                        MMA(oacc[ntd], phi, bl[s2*2], bl[s2*2+1]);
                        MMA(oacc[ntd], plo, bh[s2*2], bh[s2*2+1]);
                    }
                }
            }
        }
    }
#pragma unroll
    for(int ntd=0;ntd<8;ntd++)
#pragma unroll
        for(int half=0; half<2; half++){
            long row = (long)bb*SEQ + row0 + wid*16 + half*8 + g;
            long idx = row*D_MODEL + hh*64 + ntd*8 + t2;
            float v0 = oacc[ntd][half*2], v1 = oacc[ntd][half*2+1];
            bf16 h0,l0,h1,l1; f2pair(v0,h0,l0); f2pair(v1,h1,l1);
            *(__nv_bfloat162*)(ch + idx) = __nv_bfloat162(h0, h1);
            *(__nv_bfloat162*)(cl + idx) = __nv_bfloat162(l0, l1);
        }
}

// ---- add + LN (+ optional pair out) ----
__launch_bounds__(256)
__global__ void add_ln_k(const float* __restrict__ a, const float* __restrict__ bres,
                         const float* __restrict__ g, const float* __restrict__ be,
                         float* __restrict__ outp, bf16* __restrict__ ph, bf16* __restrict__ pl){
    const long row = blockIdx.x;
    const float* pa = a + row*D_MODEL;
    const float* pb = bres + row*D_MODEL;
    const int tid = threadIdx.x;
    __shared__ float sred[8]; __shared__ float sbc;
    float v[4]; float s = 0.f;
#pragma unroll
    for(int t=0;t<4;t++){ int c=tid+t*256; v[t]=pa[c]+pb[c]; s+=v[t]; }
#pragma unroll
    for(int o=16;o;o>>=1) s += __shfl_xor_sync(0xffffffffu, s, o);
    if((tid&31)==0) sred[tid>>5]=s;
    __syncthreads();
    if(tid==0){ float r=0.f; for(int i=0;i<8;i++) r+=sred[i]; sbc=r*(1.f/D_MODEL); }
    __syncthreads();
    const float mu = sbc;
    float q = 0.f;
#pragma unroll
    for(int t=0;t<4;t++){ float d=v[t]-mu; q+=d*d; }
#pragma unroll
    for(int o=16;o;o>>=1) q += __shfl_xor_sync(0xffffffffu, q, o);
    __syncthreads();
    if((tid&31)==0) sred[tid>>5]=q;
    __syncthreads();
    if(tid==0){ float r=0.f; for(int i=0;i<8;i++) r+=sred[i]; sbc=rsqrtf(r*(1.f/D_MODEL)+1e-5f); }
    __syncthreads();
    const float rstd = sbc;
#pragma unroll
    for(int t=0;t<4;t++){
        int c = tid+t*256;
        float o = (v[t]-mu)*rstd*g[c] + be[c];
        outp[row*D_MODEL+c] = o;
        if(ph){ bf16 h,l; f2pair(o,h,l); ph[row*D_MODEL+c]=h; pl[row*D_MODEL+c]=l; }
    }
}

// -----------------------------------------------------------------------------------
extern "C" void kernel_launch(void* const* d_in, const int* in_sizes, int n_in,
                              void* d_out, int out_size)
{
    (void)in_sizes; (void)n_in; (void)out_size;
    const float* x   = (const float*)d_in[0];
    const int*   mask= (const int*)  d_in[1];
    const float* Wq  = (const float*)d_in[2];
    const float* bq  = (const float*)d_in[3];
    const float* Wk  = (const float*)d_in[4];
    const float* bk  = (const float*)d_in[5];
    const float* Wv  = (const float*)d_in[6];
    const float* bv  = (const float*)d_in[7];
    const float* Wo  = (const float*)d_in[8];
    const float* bo  = (const float*)d_in[9];
    const float* g1  = (const float*)d_in[10];
    const float* be1 = (const float*)d_in[11];
    const float* W1  = (const float*)d_in[12];
    const float* b1  = (const float*)d_in[13];
    const float* W2  = (const float*)d_in[14];
    const float* b2  = (const float*)d_in[15];
    const float* g2  = (const float*)d_in[16];
    const float* be2 = (const float*)d_in[17];

    float* out  = (float*)d_out;
    float* attn = out + (size_t)TOK*D_MODEL;

    bf16 *xh,*xl,*wqkvh,*wqkvl,*woh,*wol,*w1h,*w1l,*w2h,*w2l;
    bf16 *qkvh,*qkvl,*vth,*vtl,*ch,*cl,*hh,*hl,*ffh,*ffl;
    float *y,*h,*bqkv,*gm,*gl;
    cudaGetSymbolAddress((void**)&xh,g_xh);       cudaGetSymbolAddress((void**)&xl,g_xl);
    cudaGetSymbolAddress((void**)&wqkvh,g_wqkvh); cudaGetSymbolAddress((void**)&wqkvl,g_wqkvl);
    cudaGetSymbolAddress((void**)&woh,g_woh);     cudaGetSymbolAddress((void**)&wol,g_wol);
    cudaGetSymbolAddress((void**)&w1h,g_w1h);     cudaGetSymbolAddress((void**)&w1l,g_w1l);
    cudaGetSymbolAddress((void**)&w2h,g_w2h);     cudaGetSymbolAddress((void**)&w2l,g_w2l);
    cudaGetSymbolAddress((void**)&qkvh,g_qkvh);   cudaGetSymbolAddress((void**)&qkvl,g_qkvl);
    cudaGetSymbolAddress((void**)&vth,g_vth);     cudaGetSymbolAddress((void**)&vtl,g_vtl);
    cudaGetSymbolAddress((void**)&ch,g_ch);       cudaGetSymbolAddress((void**)&cl,g_cl);
    cudaGetSymbolAddress((void**)&hh,g_hh);       cudaGetSymbolAddress((void**)&hl,g_hl);
    cudaGetSymbolAddress((void**)&ffh,g_ffh);     cudaGetSymbolAddress((void**)&ffl,g_ffl);
    cudaGetSymbolAddress((void**)&y,g_y);         cudaGetSymbolAddress((void**)&h,g_h);
    cudaGetSymbolAddress((void**)&bqkv,g_bqkv);
    cudaGetSymbolAddress((void**)&gm,g_m);        cudaGetSymbolAddress((void**)&gl,g_l);

    const int SM128_3 = 3 * 2*(128*72 + 128*72) * 2;  // 221184 B
    cudaFuncSetAttribute(gemm_mma<128,1,false,3,1>, cudaFuncAttributeMaxDynamicSharedMemorySize, SM128_3);
    cudaFuncSetAttribute(gemm_mma<128,0,false,3,2>, cudaFuncAttributeMaxDynamicSharedMemorySize, SM128_3);
    cudaFuncSetAttribute(gemm_mma<128,0,false,3,4>, cudaFuncAttributeMaxDynamicSharedMemorySize, SM128_3);
    cudaFuncSetAttribute(gemm_mma<128,1,true ,3,1>, cudaFuncAttributeMaxDynamicSharedMemorySize, SM128_3);
    cudaFuncSetAttribute(attn_ml_k, cudaFuncAttributeMaxDynamicSharedMemorySize, FA_SMEM);
    cudaFuncSetAttribute(attn_pv_k, cudaFuncAttributeMaxDynamicSharedMemorySize, PB_SMEM);

    const dim3 blk(256), tb(32,8);

    conv_pair_k<<<(TOK*D_MODEL)/256, blk>>>(x, xh, xl, (long)TOK*D_MODEL);
    wtrans_k<<<dim3(32,32),  tb>>>(Wq, wqkvh,              wqkvl,              D_MODEL, D_MODEL);
    wtrans_k<<<dim3(32,32),  tb>>>(Wk, wqkvh+1024*D_MODEL, wqkvl+1024*D_MODEL, D_MODEL, D_MODEL);
    wtrans_k<<<dim3(32,32),  tb>>>(Wv, wqkvh+2048*D_MODEL, wqkvl+2048*D_MODEL, D_MODEL, D_MODEL);
    wtrans_k<<<dim3(32,32),  tb>>>(Wo, woh, wol, D_MODEL, D_MODEL);
    wtrans_k<<<dim3(128,32), tb>>>(W1, w1h, w1l, D_MODEL, D_FF);
    wtrans_k<<<dim3(32,128), tb>>>(W2, w2h, w2l, D_FF, D_MODEL);
    concat_bias_k<<<12, blk>>>(bq, bk, bv, bqkv);

    gemm_mma<128,1,false,3,1><<<dim3(24,32,1), blk, SM128_3>>>(xh,xl, wqkvh,wqkvl, bqkv, nullptr, qkvh,qkvl,
        D_MODEL, D_MODEL, D_MODEL, 3072, 1.f);

    vtrans_k<<<dim3(SEQ/32, D_K/32, BH), tb>>>(qkvh+2048, qkvl+2048, 3072, vth, vtl);

    attn_ml_k<<<dim3(16,1,BH), blk, FA_SMEM>>>(qkvh, mask, gm, gl);
    // y = bo (init for atomic split-K of Wo)
    binit_k<<<(TOK*D_MODEL)/1024, blk>>>(y, bo);
    attn_pv_k<<<dim3(16,1,BH), blk, PB_SMEM>>>(qkvh, qkvl, vth, vtl, mask, gm, gl, attn, ch, cl);

    // attn_out: y += ctx @ Wo  (atomic split-K 2)
    gemm_mma<128,0,false,3,2><<<dim3(8,32,2), blk, SM128_3>>>(ch,cl, woh,wol, nullptr, y, nullptr,nullptr,
        D_MODEL, D_MODEL, D_MODEL, D_MODEL, 1.f);

    add_ln_k<<<TOK, blk>>>(x, y, g1, be1, h, hh, hl);

    gemm_mma<128,1,true,3,1><<<dim3(32,32,1), blk, SM128_3>>>(hh,hl, w1h,w1l, b1, nullptr, ffh,ffl,
        D_MODEL, D_MODEL, D_MODEL, D_FF, 1.f);

    // y = b2 then y += ff @ W2 (atomic split-K 4)
    binit_k<<<(TOK*D_MODEL)/1024, blk>>>(y, b2);
    gemm_mma<128,0,false,3,4><<<dim3(8,32,4), blk, SM128_3>>>(ffh,ffl, w2h,w2l, nullptr, y, nullptr,nullptr,
        D_FF, D_FF, D_FF, D_MODEL, 1.f);

    add_ln_k<<<TOK, blk>>>(h, y, g2, be2, out, nullptr, nullptr);
}